// round 3
// baseline (speedup 1.0000x reference)
#include <cuda_runtime.h>
#include <math.h>

#define T_MAX 4096
__device__ float g_A[T_MAX * 16];     // per-step A*dt
__device__ float g_S[T_MAX * 16];     // cumsum
__device__ float g_E[T_MAX * 16];     // expm(cumsum)

// ---------------------------------------------------------------------------
// Kernel 1: per-time-step MLP -> A[t] = (MLP(t_avg) + M0) * dt
// 16 time steps per block, 128 threads. Register tile 4j x 4s.
// ---------------------------------------------------------------------------
#define SPB 16   // steps per block
__global__ void __launch_bounds__(128)
mlp_kernel(const float* __restrict__ t,
           const float* __restrict__ M0,
           const float* __restrict__ W1, const float* __restrict__ b1,
           const float* __restrict__ W2, const float* __restrict__ b2,
           const float* __restrict__ W3, const float* __restrict__ b3,
           int T) {
    int sblk = blockIdx.x;
    int tid  = threadIdx.x;   // 0..127

    __shared__ float h1s[SPB * 128];
    __shared__ float h2s[SPB * 128];
    __shared__ float W3s[128 * 16];
    __shared__ float tavg[SPB], dts[SPB];

    if (tid < SPB) {
        int i = sblk * SPB + tid;
        float tc = (i < T) ? t[i] : 1.0f;
        float tp = (i == 0) ? 0.0f : ((i - 1 < T) ? t[i - 1] : 1.0f);
        dts[tid]  = tc - tp;
        tavg[tid] = 0.5f * (tc + tp);
    }
    for (int idx = tid; idx < 128 * 16; idx += 128) W3s[idx] = W3[idx];
    __syncthreads();

    // layer 1
    {
        float w1v = W1[tid], b1v = b1[tid];
#pragma unroll
        for (int s = 0; s < SPB; s++)
            h1s[s * 128 + tid] = tanhf(tavg[s] * w1v + b1v);
    }
    __syncthreads();

    // layer 2: thread covers j4..j4+3 (outputs) x sg..sg+3 (steps)
    {
        int j4 = (tid & 31) * 4;
        int sg = (tid >> 5) * 4;
        float acc[4][4];
#pragma unroll
        for (int jj = 0; jj < 4; jj++) {
            float b = b2[j4 + jj];
#pragma unroll
            for (int ss = 0; ss < 4; ss++) acc[jj][ss] = b;
        }
#pragma unroll 4
        for (int k = 0; k < 128; k++) {
            float4 w4 = __ldg((const float4*)(W2 + k * 128 + j4));
#pragma unroll
            for (int ss = 0; ss < 4; ss++) {
                float h = h1s[(sg + ss) * 128 + k];
                acc[0][ss] = fmaf(w4.x, h, acc[0][ss]);
                acc[1][ss] = fmaf(w4.y, h, acc[1][ss]);
                acc[2][ss] = fmaf(w4.z, h, acc[2][ss]);
                acc[3][ss] = fmaf(w4.w, h, acc[3][ss]);
            }
        }
#pragma unroll
        for (int ss = 0; ss < 4; ss++) {
            float4 hv;
            hv.x = tanhf(acc[0][ss]);
            hv.y = tanhf(acc[1][ss]);
            hv.z = tanhf(acc[2][ss]);
            hv.w = tanhf(acc[3][ss]);
            *(float4*)&h2s[(sg + ss) * 128 + j4] = hv;
        }
    }
    __syncthreads();

    // layer 3: 16 p x 16 s = 256 outputs; 2 per thread
    {
        int p  = tid & 15;
        int s0 = tid >> 4;    // 0..7
        float m0v = M0[p];
        float b3v = b3[p];
#pragma unroll
        for (int pass = 0; pass < 2; pass++) {
            int s = s0 + pass * 8;
            float a = b3v;
#pragma unroll 8
            for (int k = 0; k < 128; k++)
                a = fmaf(h2s[s * 128 + k], W3s[k * 16 + p], a);
            int i = sblk * SPB + s;
            if (i < T) g_A[i * 16 + p] = (a + m0v) * dts[s];
        }
    }
}

// ---------------------------------------------------------------------------
// Kernel 2: fused prefix-sum + 4x4 expm. Single block, 512 threads.
// Two-pass scan (no per-thread local array). 16 components x 32 chunks of 64.
// Requires T <= 2048.
// ---------------------------------------------------------------------------
__device__ __forceinline__ void expm4(const float* __restrict__ src,
                                      float* __restrict__ dst) {
    float a[16];
#pragma unroll
    for (int p = 0; p < 16; p++) a[p] = src[p];

    float nrm = 0.0f;
#pragma unroll
    for (int r = 0; r < 4; r++) {
        float rs = fabsf(a[r*4]) + fabsf(a[r*4+1]) + fabsf(a[r*4+2]) + fabsf(a[r*4+3]);
        nrm = fmaxf(nrm, rs);
    }
    int s = 0;
    while (nrm > 0.5f && s < 40) { nrm *= 0.5f; s++; }
    float sc = ldexpf(1.0f, -s);
#pragma unroll
    for (int p = 0; p < 16; p++) a[p] *= sc;

    float P[16], E[16];
#pragma unroll
    for (int p = 0; p < 16; p++) { P[p] = a[p]; E[p] = a[p]; }
#pragma unroll
    for (int d = 0; d < 4; d++) E[d * 5] += 1.0f;

    for (int k = 2; k <= 12; k++) {
        float Q[16];
        float inv = 1.0f / (float)k;
#pragma unroll
        for (int r = 0; r < 4; r++)
#pragma unroll
            for (int c = 0; c < 4; c++) {
                float v = P[r*4+0]*a[0*4+c] + P[r*4+1]*a[1*4+c]
                        + P[r*4+2]*a[2*4+c] + P[r*4+3]*a[3*4+c];
                Q[r * 4 + c] = v * inv;
            }
#pragma unroll
        for (int p = 0; p < 16; p++) { P[p] = Q[p]; E[p] += Q[p]; }
    }

    for (int q = 0; q < s; q++) {
        float Q[16];
#pragma unroll
        for (int r = 0; r < 4; r++)
#pragma unroll
            for (int c = 0; c < 4; c++)
                Q[r*4+c] = E[r*4+0]*E[0*4+c] + E[r*4+1]*E[1*4+c]
                         + E[r*4+2]*E[2*4+c] + E[r*4+3]*E[3*4+c];
#pragma unroll
        for (int p = 0; p < 16; p++) E[p] = Q[p];
    }

#pragma unroll
    for (int p = 0; p < 16; p++) dst[p] = E[p];
}

#define CHUNK 64
__global__ void __launch_bounds__(512)
scan_expm_kernel(int T) {
    int tid = threadIdx.x;        // 0..511
    int c  = tid >> 5;            // component 0..15
    int ch = tid & 31;            // chunk 0..31, each CHUNK elements

    // pass 1: chunk sums
    float run = 0.0f;
    int base = ch * CHUNK;
#pragma unroll 8
    for (int e = 0; e < CHUNK; e++) {
        int i = base + e;
        if (i < T) run += g_A[i * 16 + c];
    }

    __shared__ float ps[16 * 32];
    __shared__ float off[16 * 32];
    ps[c * 32 + ch] = run;
    __syncthreads();

    if (tid < 16) {
        float s = 0.0f;
#pragma unroll
        for (int q = 0; q < 32; q++) { off[tid * 32 + q] = s; s += ps[tid * 32 + q]; }
    }
    __syncthreads();

    // pass 2: re-read (L2-resident) and write inclusive scan
    run = off[c * 32 + ch];
#pragma unroll 8
    for (int e = 0; e < CHUNK; e++) {
        int i = base + e;
        if (i < T) { run += g_A[i * 16 + c]; g_S[i * 16 + c] = run; }
    }
    __syncthreads();

    // expm: 4 matrices per thread at T=2048
    for (int i = tid; i < T; i += 512)
        expm4(&g_S[i * 16], &g_E[i * 16]);
}

// ---------------------------------------------------------------------------
// Kernel 3 (heavy): out[t,n,:] = E[t] @ x[n,:].  268 MB of streaming stores.
// ---------------------------------------------------------------------------
#define TT 16
__global__ void __launch_bounds__(256)
apply_kernel(const float* __restrict__ x,
             float4* __restrict__ out,
             int N, int T) {
    int tbase = blockIdx.y * TT;
    int n = blockIdx.x * blockDim.x + threadIdx.x;

    __shared__ float Es[TT * 16];
    int nt = T - tbase; if (nt > TT) nt = TT;
    if (threadIdx.x < nt * 16) Es[threadIdx.x] = g_E[tbase * 16 + threadIdx.x];
    __syncthreads();

    if (n >= N) return;
    float4 xv = __ldg((const float4*)x + n);

#pragma unroll
    for (int k = 0; k < TT; k++) {
        if (k >= nt) break;
        const float* e = &Es[k * 16];
        float4 o;
        o.x = e[0]  * xv.x + e[1]  * xv.y + e[2]  * xv.z + e[3]  * xv.w;
        o.y = e[4]  * xv.x + e[5]  * xv.y + e[6]  * xv.z + e[7]  * xv.w;
        o.z = e[8]  * xv.x + e[9]  * xv.y + e[10] * xv.z + e[11] * xv.w;
        o.w = e[12] * xv.x + e[13] * xv.y + e[14] * xv.z + e[15] * xv.w;
        __stcs(&out[(size_t)(tbase + k) * N + n], o);
    }
}

// ---------------------------------------------------------------------------
extern "C" void kernel_launch(void* const* d_in, const int* in_sizes, int n_in,
                              void* d_out, int out_size) {
    const float* x  = (const float*)d_in[0];
    const float* t  = (const float*)d_in[1];
    const float* M0 = (const float*)d_in[2];
    const float* W1 = (const float*)d_in[3];
    const float* b1 = (const float*)d_in[4];
    const float* W2 = (const float*)d_in[5];
    const float* b2 = (const float*)d_in[6];
    const float* W3 = (const float*)d_in[7];
    const float* b3 = (const float*)d_in[8];
    float* out = (float*)d_out;

    int N = in_sizes[0] / 4;
    int T = in_sizes[1];

    mlp_kernel<<<(T + SPB - 1) / SPB, 128>>>(t, M0, W1, b1, W2, b2, W3, b3, T);
    scan_expm_kernel<<<1, 512>>>(T);

    dim3 grid((N + 255) / 256, (T + TT - 1) / TT);
    apply_kernel<<<grid, 256>>>(x, (float4*)out, N, T);
}

// round 4
// speedup vs baseline: 1.4930x; 1.4930x over previous
#include <cuda_runtime.h>
#include <math.h>

#define T_MAX 4096
__device__ float g_A[T_MAX * 16];     // per-step A*dt
__device__ float g_S[T_MAX * 16];     // cumsum
__device__ float g_E[T_MAX * 16];     // expm(cumsum)

// ---------------------------------------------------------------------------
// Kernel 1: MLP -> A[t] = (MLP(t_avg) + M0) * dt
// SPB=8 steps per block, 256 threads -> 256 blocks (parallel slack + only
// 16 MB of W2 L2 traffic).
// ---------------------------------------------------------------------------
#define SPB 8
__global__ void __launch_bounds__(256)
mlp_kernel(const float* __restrict__ t,
           const float* __restrict__ M0,
           const float* __restrict__ W1, const float* __restrict__ b1,
           const float* __restrict__ W2, const float* __restrict__ b2,
           const float* __restrict__ W3, const float* __restrict__ b3,
           int T) {
    int sblk = blockIdx.x;
    int tid  = threadIdx.x;   // 0..255

    __shared__ float h1s[SPB * 128];
    __shared__ float h2s[SPB * 128];
    __shared__ float W3s[128 * 16];
    __shared__ float tavg[SPB], dts[SPB];

    if (tid < SPB) {
        int i = sblk * SPB + tid;
        float tc = (i < T) ? t[i] : 1.0f;
        float tp = (i == 0) ? 0.0f : ((i - 1 < T) ? t[i - 1] : 1.0f);
        dts[tid]  = tc - tp;
        tavg[tid] = 0.5f * (tc + tp);
    }
    for (int idx = tid; idx < 128 * 16; idx += 256) W3s[idx] = W3[idx];
    __syncthreads();

    // layer 1: 1024 values over 256 threads
#pragma unroll
    for (int idx = tid; idx < SPB * 128; idx += 256) {
        int s = idx >> 7, k = idx & 127;
        h1s[idx] = tanhf(tavg[s] * W1[k] + b1[k]);
    }
    __syncthreads();

    // layer 2: thread = output j (tid&127) x 4 steps (group tid>>7)
    {
        int j  = tid & 127;
        int sg = (tid >> 7) * 4;
        float b = b2[j];
        float acc0 = b, acc1 = b, acc2 = b, acc3 = b;
#pragma unroll 4
        for (int k = 0; k < 128; k++) {
            float w = __ldg(W2 + k * 128 + j);
            acc0 = fmaf(w, h1s[(sg + 0) * 128 + k], acc0);
            acc1 = fmaf(w, h1s[(sg + 1) * 128 + k], acc1);
            acc2 = fmaf(w, h1s[(sg + 2) * 128 + k], acc2);
            acc3 = fmaf(w, h1s[(sg + 3) * 128 + k], acc3);
        }
        h2s[(sg + 0) * 128 + j] = tanhf(acc0);
        h2s[(sg + 1) * 128 + j] = tanhf(acc1);
        h2s[(sg + 2) * 128 + j] = tanhf(acc2);
        h2s[(sg + 3) * 128 + j] = tanhf(acc3);
    }
    __syncthreads();

    // layer 3: 8 steps x 16 outputs = 128; threads 0..127, 4-way ILP
    if (tid < 128) {
        int p = tid & 15;
        int s = tid >> 4;
        float a0 = b3[p], a1 = 0.f, a2 = 0.f, a3 = 0.f;
#pragma unroll 8
        for (int k = 0; k < 128; k += 4) {
            a0 = fmaf(h2s[s * 128 + k + 0], W3s[(k + 0) * 16 + p], a0);
            a1 = fmaf(h2s[s * 128 + k + 1], W3s[(k + 1) * 16 + p], a1);
            a2 = fmaf(h2s[s * 128 + k + 2], W3s[(k + 2) * 16 + p], a2);
            a3 = fmaf(h2s[s * 128 + k + 3], W3s[(k + 3) * 16 + p], a3);
        }
        float a = (a0 + a1) + (a2 + a3);
        int i = sblk * SPB + s;
        if (i < T) g_A[i * 16 + p] = (a + M0[p]) * dts[s];
    }
}

// ---------------------------------------------------------------------------
// Kernel 2: prefix sum only. One block, 256 threads (16 comps x 16 chunks).
// Two-pass, L2 resident. ~2 us.
// ---------------------------------------------------------------------------
__global__ void __launch_bounds__(256)
scan_kernel(int T) {
    int tid = threadIdx.x;
    int c  = tid >> 4;            // component 0..15
    int ch = tid & 15;            // chunk 0..15
    int CH = (T + 15) >> 4;       // chunk length (128 at T=2048)
    int base = ch * CH;

    float run = 0.0f;
    for (int e = 0; e < CH; e++) {
        int i = base + e;
        if (i < T) run += g_A[i * 16 + c];
    }

    __shared__ float ps[16 * 16];
    __shared__ float off[16 * 16];
    ps[c * 16 + ch] = run;
    __syncthreads();

    if (tid < 16) {
        float s = 0.0f;
#pragma unroll
        for (int q = 0; q < 16; q++) { off[tid * 16 + q] = s; s += ps[tid * 16 + q]; }
    }
    __syncthreads();

    run = off[c * 16 + ch];
    for (int e = 0; e < CH; e++) {
        int i = base + e;
        if (i < T) { run += g_A[i * 16 + c]; g_S[i * 16 + c] = run; }
    }
}

// ---------------------------------------------------------------------------
// Kernel 3: 4x4 expm, one thread per matrix, fully parallel.
// ---------------------------------------------------------------------------
__global__ void __launch_bounds__(128)
expm_kernel(int T) {
    int i = blockIdx.x * 128 + threadIdx.x;
    if (i >= T) return;

    float a[16];
#pragma unroll
    for (int p = 0; p < 16; p++) a[p] = g_S[i * 16 + p];

    float nrm = 0.0f;
#pragma unroll
    for (int r = 0; r < 4; r++) {
        float rs = fabsf(a[r*4]) + fabsf(a[r*4+1]) + fabsf(a[r*4+2]) + fabsf(a[r*4+3]);
        nrm = fmaxf(nrm, rs);
    }
    int s = 0;
    while (nrm > 0.5f && s < 40) { nrm *= 0.5f; s++; }
    float sc = ldexpf(1.0f, -s);
#pragma unroll
    for (int p = 0; p < 16; p++) a[p] *= sc;

    float P[16], E[16];
#pragma unroll
    for (int p = 0; p < 16; p++) { P[p] = a[p]; E[p] = a[p]; }
#pragma unroll
    for (int d = 0; d < 4; d++) E[d * 5] += 1.0f;

    for (int k = 2; k <= 12; k++) {
        float Q[16];
        float inv = 1.0f / (float)k;
#pragma unroll
        for (int r = 0; r < 4; r++)
#pragma unroll
            for (int c = 0; c < 4; c++) {
                float v = P[r*4+0]*a[0*4+c] + P[r*4+1]*a[1*4+c]
                        + P[r*4+2]*a[2*4+c] + P[r*4+3]*a[3*4+c];
                Q[r * 4 + c] = v * inv;
            }
#pragma unroll
        for (int p = 0; p < 16; p++) { P[p] = Q[p]; E[p] += Q[p]; }
    }

    for (int q = 0; q < s; q++) {
        float Q[16];
#pragma unroll
        for (int r = 0; r < 4; r++)
#pragma unroll
            for (int c = 0; c < 4; c++)
                Q[r*4+c] = E[r*4+0]*E[0*4+c] + E[r*4+1]*E[1*4+c]
                         + E[r*4+2]*E[2*4+c] + E[r*4+3]*E[3*4+c];
#pragma unroll
        for (int p = 0; p < 16; p++) E[p] = Q[p];
    }

#pragma unroll
    for (int p = 0; p < 16; p++) g_E[i * 16 + p] = E[p];
}

// ---------------------------------------------------------------------------
// Kernel 4 (heavy): out[t,n,:] = E[t] @ x[n,:].  268 MB streaming stores.
// ---------------------------------------------------------------------------
#define TT 16
__global__ void __launch_bounds__(256)
apply_kernel(const float* __restrict__ x,
             float4* __restrict__ out,
             int N, int T) {
    int tbase = blockIdx.y * TT;
    int n = blockIdx.x * blockDim.x + threadIdx.x;

    __shared__ float Es[TT * 16];
    int nt = T - tbase; if (nt > TT) nt = TT;
    if (threadIdx.x < nt * 16) Es[threadIdx.x] = g_E[tbase * 16 + threadIdx.x];
    __syncthreads();

    if (n >= N) return;
    float4 xv = __ldg((const float4*)x + n);

#pragma unroll
    for (int k = 0; k < TT; k++) {
        if (k >= nt) break;
        const float* e = &Es[k * 16];
        float4 o;
        o.x = e[0]  * xv.x + e[1]  * xv.y + e[2]  * xv.z + e[3]  * xv.w;
        o.y = e[4]  * xv.x + e[5]  * xv.y + e[6]  * xv.z + e[7]  * xv.w;
        o.z = e[8]  * xv.x + e[9]  * xv.y + e[10] * xv.z + e[11] * xv.w;
        o.w = e[12] * xv.x + e[13] * xv.y + e[14] * xv.z + e[15] * xv.w;
        __stcs(&out[(size_t)(tbase + k) * N + n], o);
    }
}

// ---------------------------------------------------------------------------
extern "C" void kernel_launch(void* const* d_in, const int* in_sizes, int n_in,
                              void* d_out, int out_size) {
    const float* x  = (const float*)d_in[0];
    const float* t  = (const float*)d_in[1];
    const float* M0 = (const float*)d_in[2];
    const float* W1 = (const float*)d_in[3];
    const float* b1 = (const float*)d_in[4];
    const float* W2 = (const float*)d_in[5];
    const float* b2 = (const float*)d_in[6];
    const float* W3 = (const float*)d_in[7];
    const float* b3 = (const float*)d_in[8];
    float* out = (float*)d_out;

    int N = in_sizes[0] / 4;
    int T = in_sizes[1];

    mlp_kernel<<<(T + SPB - 1) / SPB, 256>>>(t, M0, W1, b1, W2, b2, W3, b3, T);
    scan_kernel<<<1, 256>>>(T);
    expm_kernel<<<(T + 127) / 128, 128>>>(T);

    dim3 grid((N + 255) / 256, (T + TT - 1) / TT);
    apply_kernel<<<grid, 256>>>(x, (float4*)out, N, T);
}

// round 5
// speedup vs baseline: 2.4326x; 1.6294x over previous
#include <cuda_runtime.h>
#include <math.h>

#define T_MAX 2048
#define PB   128          // prep blocks (must be <= SM count for barrier safety)
#define SPB  16           // steps per block; PB*SPB == T_MAX

__device__ float g_E[T_MAX * 16];          // expm(cumsum)
__device__ float g_csum[16 * PB];          // per-block per-component chunk sums
__device__ unsigned g_bar;                 // monotonic grid-barrier counter

// ---------------------------------------------------------------------------
// Fused prep: MLP -> A*dt (SMEM) -> chunk sums -> grid barrier -> offsets ->
// local scan -> expm -> g_E.  One launch.
// ---------------------------------------------------------------------------
__global__ void __launch_bounds__(512, 1)
prep_kernel(const float* __restrict__ t,
            const float* __restrict__ M0,
            const float* __restrict__ W1, const float* __restrict__ b1,
            const float* __restrict__ W2, const float* __restrict__ b2,
            const float* __restrict__ W3, const float* __restrict__ b3,
            int T) {
    int b   = blockIdx.x;
    int tid = threadIdx.x;    // 0..511

    __shared__ float h1s[SPB * 128];
    __shared__ float h2s[SPB * 128];
    __shared__ float W3s[128 * 16];
    __shared__ float tavg[SPB], dts[SPB];
    __shared__ float As[SPB * 16];   // A*dt for this block's steps   [s][p]
    __shared__ float Ss[SPB * 16];   // cumsum for this block's steps [s][c]

    if (tid < SPB) {
        int i = b * SPB + tid;
        float tc = (i < T) ? t[i] : 1.0f;
        float tp = (i == 0) ? 0.0f : ((i - 1 < T) ? t[i - 1] : 1.0f);
        dts[tid]  = tc - tp;
        tavg[tid] = 0.5f * (tc + tp);
    }
    for (int idx = tid; idx < 128 * 16; idx += 512) W3s[idx] = W3[idx];
    __syncthreads();

    // layer 1: SPB*128 = 2048 values
    for (int idx = tid; idx < SPB * 128; idx += 512) {
        int s = idx >> 7, k = idx & 127;
        h1s[idx] = tanhf(tavg[s] * W1[k] + b1[k]);
    }
    __syncthreads();

    // layer 2: thread = output j (tid&127), step group sg (tid>>7)*4
    {
        int j  = tid & 127;
        int sg = (tid >> 7) * 4;
        float bb = b2[j];
        float a0 = bb, a1 = bb, a2 = bb, a3 = bb;
#pragma unroll 8
        for (int k = 0; k < 128; k++) {
            float w = __ldg(W2 + k * 128 + j);     // coalesced across warp
            a0 = fmaf(w, h1s[(sg + 0) * 128 + k], a0);
            a1 = fmaf(w, h1s[(sg + 1) * 128 + k], a1);
            a2 = fmaf(w, h1s[(sg + 2) * 128 + k], a2);
            a3 = fmaf(w, h1s[(sg + 3) * 128 + k], a3);
        }
        h2s[(sg + 0) * 128 + j] = tanhf(a0);
        h2s[(sg + 1) * 128 + j] = tanhf(a1);
        h2s[(sg + 2) * 128 + j] = tanhf(a2);
        h2s[(sg + 3) * 128 + j] = tanhf(a3);
    }
    __syncthreads();

    // layer 3: SPB*16 = 256 outputs, one per thread (threads 0..255)
    if (tid < SPB * 16) {
        int s = tid >> 4;
        int p = tid & 15;
        float a0 = b3[p], a1 = 0.f, a2 = 0.f, a3 = 0.f;
#pragma unroll 8
        for (int k = 0; k < 128; k += 4) {
            a0 = fmaf(h2s[s * 128 + k + 0], W3s[(k + 0) * 16 + p], a0);
            a1 = fmaf(h2s[s * 128 + k + 1], W3s[(k + 1) * 16 + p], a1);
            a2 = fmaf(h2s[s * 128 + k + 2], W3s[(k + 2) * 16 + p], a2);
            a3 = fmaf(h2s[s * 128 + k + 3], W3s[(k + 3) * 16 + p], a3);
        }
        As[s * 16 + p] = ((a0 + a1) + (a2 + a3) + M0[p]) * dts[s];
    }
    __syncthreads();

    // chunk sums: thread c sums this block's steps for component c
    if (tid < 16) {
        int c = tid;
        float sum = 0.0f;
#pragma unroll
        for (int e = 0; e < SPB; e++) {
            int i = b * SPB + e;
            if (i < T) sum += As[e * 16 + c];
        }
        g_csum[c * PB + b] = sum;
    }

    // ---- grid barrier (monotonic counter: safe across graph replays) ----
    __syncthreads();
    if (tid == 0) {
        __threadfence();
        unsigned arrive = atomicAdd(&g_bar, 1u) + 1u;
        unsigned target = ((arrive + PB - 1u) / PB) * PB;
        while (atomicAdd(&g_bar, 0u) < target) { }
    }
    __syncthreads();
    __threadfence();

    // offsets (redundant per block) + local inclusive scan
    if (tid < 16) {
        int c = tid;
        float off = 0.0f;
        for (int q = 0; q < b; q++) off += g_csum[c * PB + q];
        float run = off;
#pragma unroll
        for (int e = 0; e < SPB; e++) {
            run += As[e * 16 + c];
            Ss[e * 16 + c] = run;
        }
    }
    __syncthreads();

    // expm: threads 0..15, one matrix each
    if (tid < SPB) {
        int i = b * SPB + tid;
        if (i < T) {
            float a[16];
#pragma unroll
            for (int p = 0; p < 16; p++) a[p] = Ss[tid * 16 + p];

            float nrm = 0.0f;
#pragma unroll
            for (int r = 0; r < 4; r++) {
                float rs = fabsf(a[r*4]) + fabsf(a[r*4+1]) + fabsf(a[r*4+2]) + fabsf(a[r*4+3]);
                nrm = fmaxf(nrm, rs);
            }
            int sq = 0;
            while (nrm > 0.5f && sq < 40) { nrm *= 0.5f; sq++; }
            float sc = ldexpf(1.0f, -sq);
#pragma unroll
            for (int p = 0; p < 16; p++) a[p] *= sc;

            float P[16], E[16];
#pragma unroll
            for (int p = 0; p < 16; p++) { P[p] = a[p]; E[p] = a[p]; }
#pragma unroll
            for (int d = 0; d < 4; d++) E[d * 5] += 1.0f;

            for (int k = 2; k <= 12; k++) {
                float Q[16];
                float inv = 1.0f / (float)k;
#pragma unroll
                for (int r = 0; r < 4; r++)
#pragma unroll
                    for (int c = 0; c < 4; c++)
                        Q[r*4+c] = (P[r*4+0]*a[0*4+c] + P[r*4+1]*a[1*4+c]
                                  + P[r*4+2]*a[2*4+c] + P[r*4+3]*a[3*4+c]) * inv;
#pragma unroll
                for (int p = 0; p < 16; p++) { P[p] = Q[p]; E[p] += Q[p]; }
            }
            for (int q = 0; q < sq; q++) {
                float Q[16];
#pragma unroll
                for (int r = 0; r < 4; r++)
#pragma unroll
                    for (int c = 0; c < 4; c++)
                        Q[r*4+c] = E[r*4+0]*E[0*4+c] + E[r*4+1]*E[1*4+c]
                                 + E[r*4+2]*E[2*4+c] + E[r*4+3]*E[3*4+c];
#pragma unroll
                for (int p = 0; p < 16; p++) E[p] = Q[p];
            }
#pragma unroll
            for (int p = 0; p < 16; p++) g_E[i * 16 + p] = E[p];
        }
    }
}

// ---------------------------------------------------------------------------
// Apply (heavy): out[t,n,:] = E[t] @ x[n,:].  268 MB streaming stores.
// ---------------------------------------------------------------------------
#define TT 16
__global__ void __launch_bounds__(256)
apply_kernel(const float* __restrict__ x,
             float4* __restrict__ out,
             int N, int T) {
    int tbase = blockIdx.y * TT;
    int n = blockIdx.x * blockDim.x + threadIdx.x;

    __shared__ float Es[TT * 16];
    int nt = T - tbase; if (nt > TT) nt = TT;
    if (threadIdx.x < nt * 16) Es[threadIdx.x] = g_E[tbase * 16 + threadIdx.x];
    __syncthreads();

    if (n >= N) return;
    float4 xv = __ldg((const float4*)x + n);

#pragma unroll
    for (int k = 0; k < TT; k++) {
        if (k >= nt) break;
        const float* e = &Es[k * 16];
        float4 o;
        o.x = e[0]  * xv.x + e[1]  * xv.y + e[2]  * xv.z + e[3]  * xv.w;
        o.y = e[4]  * xv.x + e[5]  * xv.y + e[6]  * xv.z + e[7]  * xv.w;
        o.z = e[8]  * xv.x + e[9]  * xv.y + e[10] * xv.z + e[11] * xv.w;
        o.w = e[12] * xv.x + e[13] * xv.y + e[14] * xv.z + e[15] * xv.w;
        __stcs(&out[(size_t)(tbase + k) * N + n], o);
    }
}

// ---------------------------------------------------------------------------
extern "C" void kernel_launch(void* const* d_in, const int* in_sizes, int n_in,
                              void* d_out, int out_size) {
    const float* x  = (const float*)d_in[0];
    const float* t  = (const float*)d_in[1];
    const float* M0 = (const float*)d_in[2];
    const float* W1 = (const float*)d_in[3];
    const float* b1 = (const float*)d_in[4];
    const float* W2 = (const float*)d_in[5];
    const float* b2 = (const float*)d_in[6];
    const float* W3 = (const float*)d_in[7];
    const float* b3 = (const float*)d_in[8];
    float* out = (float*)d_out;

    int N = in_sizes[0] / 4;
    int T = in_sizes[1];    // must be <= PB*SPB (2048)

    prep_kernel<<<PB, 512>>>(t, M0, W1, b1, W2, b2, W3, b3, T);

    dim3 grid((N + 255) / 256, (T + TT - 1) / TT);
    apply_kernel<<<grid, 256>>>(x, (float4*)out, N, T);
}

// round 6
// speedup vs baseline: 2.4410x; 1.0035x over previous
#include <cuda_runtime.h>
#include <math.h>

#define T_MAX 2048
#define PB   128          // blocks (<= SM count: all co-resident, barrier-safe)
#define SPB  16           // steps per block; PB*SPB == T_MAX
#define NTH  512

__device__ float g_csum[16 * PB];          // per-block per-component chunk sums
__device__ unsigned g_bar;                 // monotonic grid-barrier counter

// ---------------------------------------------------------------------------
// ONE kernel: MLP -> A*dt (SMEM) -> chunk sums -> grid barrier -> offsets ->
// local scan -> expm (SMEM) -> stream out[t0..t0+15, :, :].
// ---------------------------------------------------------------------------
__global__ void __launch_bounds__(NTH, 1)
fused_kernel(const float* __restrict__ x,
             const float* __restrict__ t,
             const float* __restrict__ M0,
             const float* __restrict__ W1, const float* __restrict__ b1,
             const float* __restrict__ W2, const float* __restrict__ b2,
             const float* __restrict__ W3, const float* __restrict__ b3,
             float4* __restrict__ out,
             int N, int T) {
    int b   = blockIdx.x;
    int tid = threadIdx.x;    // 0..511

    __shared__ float h1s[SPB * 128];
    __shared__ float h2s[SPB * 128];
    __shared__ float W3s[128 * 16];
    __shared__ float tavg[SPB], dts[SPB];
    __shared__ float As[SPB * 16];   // A*dt   [s][p]
    __shared__ float Es[SPB * 16];   // expm   [s][p]

    if (tid < SPB) {
        int i = b * SPB + tid;
        float tc = (i < T) ? t[i] : 1.0f;
        float tp = (i == 0) ? 0.0f : ((i - 1 < T) ? t[i - 1] : 1.0f);
        dts[tid]  = tc - tp;
        tavg[tid] = 0.5f * (tc + tp);
    }
    for (int idx = tid; idx < 128 * 16; idx += NTH) W3s[idx] = W3[idx];
    __syncthreads();

    // layer 1: SPB*128 = 2048 values
    for (int idx = tid; idx < SPB * 128; idx += NTH) {
        int s = idx >> 7, k = idx & 127;
        h1s[idx] = tanhf(tavg[s] * W1[k] + b1[k]);
    }
    __syncthreads();

    // layer 2: thread = output j (tid&127), step group (tid>>7)*4
    {
        int j  = tid & 127;
        int sg = (tid >> 7) * 4;
        float bb = b2[j];
        float a0 = bb, a1 = bb, a2 = bb, a3 = bb;
#pragma unroll 8
        for (int k = 0; k < 128; k++) {
            float w = __ldg(W2 + k * 128 + j);
            a0 = fmaf(w, h1s[(sg + 0) * 128 + k], a0);
            a1 = fmaf(w, h1s[(sg + 1) * 128 + k], a1);
            a2 = fmaf(w, h1s[(sg + 2) * 128 + k], a2);
            a3 = fmaf(w, h1s[(sg + 3) * 128 + k], a3);
        }
        h2s[(sg + 0) * 128 + j] = tanhf(a0);
        h2s[(sg + 1) * 128 + j] = tanhf(a1);
        h2s[(sg + 2) * 128 + j] = tanhf(a2);
        h2s[(sg + 3) * 128 + j] = tanhf(a3);
    }
    __syncthreads();

    // layer 3: SPB*16 = 256 outputs, one per thread
    if (tid < SPB * 16) {
        int s = tid >> 4;
        int p = tid & 15;
        float a0 = b3[p], a1 = 0.f, a2 = 0.f, a3 = 0.f;
#pragma unroll 8
        for (int k = 0; k < 128; k += 4) {
            a0 = fmaf(h2s[s * 128 + k + 0], W3s[(k + 0) * 16 + p], a0);
            a1 = fmaf(h2s[s * 128 + k + 1], W3s[(k + 1) * 16 + p], a1);
            a2 = fmaf(h2s[s * 128 + k + 2], W3s[(k + 2) * 16 + p], a2);
            a3 = fmaf(h2s[s * 128 + k + 3], W3s[(k + 3) * 16 + p], a3);
        }
        As[s * 16 + p] = ((a0 + a1) + (a2 + a3) + M0[p]) * dts[s];
    }
    __syncthreads();

    // chunk sums for this block's steps
    if (tid < 16) {
        int c = tid;
        float sum = 0.0f;
#pragma unroll
        for (int e = 0; e < SPB; e++) {
            int i = b * SPB + e;
            if (i < T) sum += As[e * 16 + c];
        }
        g_csum[c * PB + b] = sum;
    }

    // ---- grid barrier (monotonic counter: graph-replay safe) ----
    __syncthreads();
    if (tid == 0) {
        __threadfence();
        unsigned arrive = atomicAdd(&g_bar, 1u) + 1u;
        unsigned target = ((arrive + PB - 1u) / PB) * PB;
        while (atomicAdd(&g_bar, 0u) < target) { __nanosleep(64); }
    }
    __syncthreads();
    __threadfence();

    // offsets + local scan + expm: threads 0..15, one component each for the
    // scan, then one matrix each for expm.
    if (tid < 16) {
        int c = tid;
        float off = 0.0f;
        for (int q = 0; q < b; q++) off += g_csum[c * PB + q];
        float run = off;
#pragma unroll
        for (int e = 0; e < SPB; e++) {
            run += As[e * 16 + c];
            As[e * 16 + c] = run;   // reuse As as cumsum buffer
        }
    }
    __syncthreads();

    if (tid < SPB) {
        float a[16];
#pragma unroll
        for (int p = 0; p < 16; p++) a[p] = As[tid * 16 + p];

        float nrm = 0.0f;
#pragma unroll
        for (int r = 0; r < 4; r++) {
            float rs = fabsf(a[r*4]) + fabsf(a[r*4+1]) + fabsf(a[r*4+2]) + fabsf(a[r*4+3]);
            nrm = fmaxf(nrm, rs);
        }
        int sq = 0;
        while (nrm > 0.5f && sq < 40) { nrm *= 0.5f; sq++; }
        float sc = ldexpf(1.0f, -sq);
#pragma unroll
        for (int p = 0; p < 16; p++) a[p] *= sc;

        float P[16], E[16];
#pragma unroll
        for (int p = 0; p < 16; p++) { P[p] = a[p]; E[p] = a[p]; }
#pragma unroll
        for (int d = 0; d < 4; d++) E[d * 5] += 1.0f;

        for (int k = 2; k <= 12; k++) {
            float Q[16];
            float inv = 1.0f / (float)k;
#pragma unroll
            for (int r = 0; r < 4; r++)
#pragma unroll
                for (int c = 0; c < 4; c++)
                    Q[r*4+c] = (P[r*4+0]*a[0*4+c] + P[r*4+1]*a[1*4+c]
                              + P[r*4+2]*a[2*4+c] + P[r*4+3]*a[3*4+c]) * inv;
#pragma unroll
            for (int p = 0; p < 16; p++) { P[p] = Q[p]; E[p] += Q[p]; }
        }
        for (int q = 0; q < sq; q++) {
            float Q[16];
#pragma unroll
            for (int r = 0; r < 4; r++)
#pragma unroll
                for (int c = 0; c < 4; c++)
                    Q[r*4+c] = E[r*4+0]*E[0*4+c] + E[r*4+1]*E[1*4+c]
                             + E[r*4+2]*E[2*4+c] + E[r*4+3]*E[3*4+c];
#pragma unroll
            for (int p = 0; p < 16; p++) E[p] = Q[p];
        }
#pragma unroll
        for (int p = 0; p < 16; p++) Es[tid * 16 + p] = E[p];
    }
    __syncthreads();

    // ---- apply: stream this block's 16 output rows (2 MB of stores) ----
    const float4* x4 = (const float4*)x;
    int t0 = b * SPB;
    int nsteps = T - t0; if (nsteps > SPB) nsteps = SPB;
    if (nsteps <= 0) return;

    for (int n = tid; n < N; n += NTH) {
        float4 xv = __ldg(x4 + n);
#pragma unroll
        for (int s = 0; s < SPB; s++) {
            if (s >= nsteps) break;
            const float* e = &Es[s * 16];
            float4 o;
            o.x = e[0]  * xv.x + e[1]  * xv.y + e[2]  * xv.z + e[3]  * xv.w;
            o.y = e[4]  * xv.x + e[5]  * xv.y + e[6]  * xv.z + e[7]  * xv.w;
            o.z = e[8]  * xv.x + e[9]  * xv.y + e[10] * xv.z + e[11] * xv.w;
            o.w = e[12] * xv.x + e[13] * xv.y + e[14] * xv.z + e[15] * xv.w;
            __stcs(&out[(size_t)(t0 + s) * N + n], o);
        }
    }
}

// ---------------------------------------------------------------------------
extern "C" void kernel_launch(void* const* d_in, const int* in_sizes, int n_in,
                              void* d_out, int out_size) {
    const float* x  = (const float*)d_in[0];
    const float* t  = (const float*)d_in[1];
    const float* M0 = (const float*)d_in[2];
    const float* W1 = (const float*)d_in[3];
    const float* b1 = (const float*)d_in[4];
    const float* W2 = (const float*)d_in[5];
    const float* b2 = (const float*)d_in[6];
    const float* W3 = (const float*)d_in[7];
    const float* b3 = (const float*)d_in[8];
    float* out = (float*)d_out;

    int N = in_sizes[0] / 4;
    int T = in_sizes[1];    // must be <= PB*SPB (2048)

    fused_kernel<<<PB, NTH>>>(x, t, M0, W1, b1, W2, b2, W3, b3,
                              (float4*)out, N, T);
}